// round 2
// baseline (speedup 1.0000x reference)
#include <cuda_runtime.h>
#include <cstdint>

#define KDIM   4096
#define BATCH  16384
#define CRC    24
#define OUTW   (KDIM + CRC)        // 4120
#define NBLOCK 2048                // BATCH / 8 rows-per-block (one row per warp)

// Scratch: packed g_mat masks, bit j of g_masks[k] = g_mat[k][j]
__device__ uint32_t g_masks[KDIM];

__global__ void __launch_bounds__(256) pack_masks_kernel(const float* __restrict__ g_mat) {
    int k = blockIdx.x * blockDim.x + threadIdx.x;
    if (k < KDIM) {
        uint32_t m = 0;
        #pragma unroll
        for (int j = 0; j < CRC; j++) {
            if (g_mat[k * CRC + j] != 0.0f) m |= (1u << j);
        }
        g_masks[k] = m;
    }
}

__global__ void __launch_bounds__(256) crc_encode_kernel(const float* __restrict__ in,
                                                         float* __restrict__ out) {
    // Shared copy of the 16KB mask table, stored as uint4 for conflict-free LDS.128
    __shared__ uint4 smasks[KDIM / 4];   // 1024 uint4 = 16KB

    const int tid  = threadIdx.x;
    const int lane = tid & 31;
    const int warp = tid >> 5;

    // Cooperative load of masks (global array is L2-resident: 16KB)
    const uint4* gm4 = reinterpret_cast<const uint4*>(g_masks);
    #pragma unroll
    for (int i = tid; i < KDIM / 4; i += 256)
        smasks[i] = gm4[i];
    __syncthreads();

    // One row per warp: 8 rows per block
    const int row = blockIdx.x * 8 + warp;

    const float4* __restrict__ inrow  =
        reinterpret_cast<const float4*>(in + (size_t)row * KDIM);
    float4* __restrict__ outrow =
        reinterpret_cast<float4*>(out + (size_t)row * OUTW);

    uint32_t acc = 0;

    // 4096 floats / warp = 1024 float4 / warp = 32 float4 per lane
    #pragma unroll 8
    for (int it = 0; it < 32; it++) {
        const int f = it * 32 + lane;      // float4 index within row
        float4 v = inrow[f];
        outrow[f] = v;                      // streaming copy of payload
        uint4 m = smasks[f];                // masks for elements 4f..4f+3
        if (v.x != 0.0f) acc ^= m.x;
        if (v.y != 0.0f) acc ^= m.y;
        if (v.z != 0.0f) acc ^= m.z;
        if (v.w != 0.0f) acc ^= m.w;
    }

    // XOR-reduce across the warp
    #pragma unroll
    for (int o = 16; o > 0; o >>= 1)
        acc ^= __shfl_xor_sync(0xFFFFFFFFu, acc, o);

    // lanes 0..23 emit the CRC bits as floats
    if (lane < CRC)
        out[(size_t)row * OUTW + KDIM + lane] = (float)((acc >> lane) & 1u);
}

extern "C" void kernel_launch(void* const* d_in, const int* in_sizes, int n_in,
                              void* d_out, int out_size) {
    const float* bits  = (const float*)d_in[0];   // [BATCH, KDIM]
    const float* g_mat = (const float*)d_in[1];   // [KDIM, CRC]
    float* out = (float*)d_out;                   // [BATCH, OUTW]

    pack_masks_kernel<<<(KDIM + 255) / 256, 256>>>(g_mat);
    crc_encode_kernel<<<NBLOCK, 256>>>(bits, out);
}

// round 3
// speedup vs baseline: 1.0228x; 1.0228x over previous
#include <cuda_runtime.h>
#include <cstdint>

#define KDIM   4096
#define BATCH  16384
#define CRC    24
#define OUTW   (KDIM + CRC)        // 4120
#define NBLOCK 2048                // one row per warp, 8 warps per block

// Packed g_mat masks: bit j of g_masks[k] = (g_mat[k][j] != 0)
__device__ uint32_t g_masks[KDIM];

// ---------------------------------------------------------------------------
// Pack kernel: ballot-based, fully coalesced. 4 blocks x 256 threads.
// Block b handles masks [b*1024, (b+1)*1024) = bitstream floats [b*24576, ...).
// ---------------------------------------------------------------------------
__global__ void __launch_bounds__(256) pack_masks_kernel(const float* __restrict__ g_mat) {
    __shared__ uint32_t words[776];           // 768 used + pad for funnelshift read
    const int t    = threadIdx.x;
    const int lane = t & 31;
    const int base = blockIdx.x * (1024 * CRC);   // 24576 floats per block

    #pragma unroll
    for (int r = 0; r < 96; r++) {
        int idx = r * 256 + t;                // local float index, coalesced
        float v = g_mat[base + idx];
        unsigned b = __ballot_sync(0xFFFFFFFFu, v != 0.0f);
        if (lane == 0) words[idx >> 5] = b;   // idx>>5 uniform within the warp
    }
    __syncthreads();

    #pragma unroll
    for (int i = 0; i < 4; i++) {
        int klocal = t * 4 + i;
        int bitpos = klocal * CRC;
        uint32_t lo = words[bitpos >> 5];
        uint32_t hi = words[(bitpos >> 5) + 1];   // may read pad; masked below
        g_masks[blockIdx.x * 1024 + klocal] =
            __funnelshift_r(lo, hi, bitpos & 31) & 0x00FFFFFFu;
    }
}

// ---------------------------------------------------------------------------
// Main kernel: fused copy + CRC. One row per warp, depth-4 load pipeline,
// streaming cache hints. Launched with PDL; waits for pack before touching
// g_masks.
// ---------------------------------------------------------------------------
__global__ void __launch_bounds__(256) crc_encode_kernel(const float* __restrict__ in,
                                                         float* __restrict__ out) {
    // Wait for the pack kernel (PDL). No-op if launched without PDL.
    cudaGridDependencySynchronize();

    __shared__ uint4 smasks[KDIM / 4];        // 16 KB

    const int tid  = threadIdx.x;
    const int lane = tid & 31;
    const int warp = tid >> 5;

    const uint4* gm4 = reinterpret_cast<const uint4*>(g_masks);
    #pragma unroll
    for (int i = tid; i < KDIM / 4; i += 256)
        smasks[i] = gm4[i];
    __syncthreads();

    const int row = blockIdx.x * 8 + warp;

    const float4* __restrict__ inrow =
        reinterpret_cast<const float4*>(in + (size_t)row * KDIM);
    float4* __restrict__ outrow =
        reinterpret_cast<float4*>(out + (size_t)row * OUTW);

    uint32_t acc = 0;
    float4 buf[4];

    // Prologue: 4 loads in flight
    #pragma unroll
    for (int p = 0; p < 4; p++)
        buf[p] = __ldcs(inrow + p * 32 + lane);

    // 32 float4 per lane, depth-4 software pipeline
    #pragma unroll
    for (int it = 0; it < 32; it++) {
        float4 v = buf[it & 3];
        if (it < 28)
            buf[it & 3] = __ldcs(inrow + (it + 4) * 32 + lane);
        uint4 m = smasks[it * 32 + lane];
        __stcs(outrow + it * 32 + lane, v);
        if (v.x != 0.0f) acc ^= m.x;
        if (v.y != 0.0f) acc ^= m.y;
        if (v.z != 0.0f) acc ^= m.z;
        if (v.w != 0.0f) acc ^= m.w;
    }

    // XOR-reduce across the warp
    #pragma unroll
    for (int o = 16; o > 0; o >>= 1)
        acc ^= __shfl_xor_sync(0xFFFFFFFFu, acc, o);

    if (lane < CRC)
        out[(size_t)row * OUTW + KDIM + lane] = (float)((acc >> lane) & 1u);
}

extern "C" void kernel_launch(void* const* d_in, const int* in_sizes, int n_in,
                              void* d_out, int out_size) {
    const float* bits  = (const float*)d_in[0];   // [BATCH, KDIM]
    const float* g_mat = (const float*)d_in[1];   // [KDIM, CRC]
    float* out = (float*)d_out;                   // [BATCH, OUTW]

    pack_masks_kernel<<<4, 256>>>(g_mat);

    // PDL launch: crc blocks go resident early, spin in
    // cudaGridDependencySynchronize() until pack completes.
    cudaLaunchConfig_t cfg = {};
    cfg.gridDim  = dim3(NBLOCK);
    cfg.blockDim = dim3(256);
    cfg.dynamicSmemBytes = 0;
    cfg.stream = 0;
    cudaLaunchAttribute attrs[1];
    attrs[0].id = cudaLaunchAttributeProgrammaticStreamSerialization;
    attrs[0].val.programmaticStreamSerializationAllowed = 1;
    cfg.attrs = attrs;
    cfg.numAttrs = 1;

    cudaError_t e = cudaLaunchKernelEx(&cfg, crc_encode_kernel, bits, out);
    if (e != cudaSuccess) {
        // Fallback: plain serialized launch (still correct)
        crc_encode_kernel<<<NBLOCK, 256>>>(bits, out);
    }
}